// round 16
// baseline (speedup 1.0000x reference)
#include <cuda_runtime.h>
#include <math.h>

#define BX 32
#define BY 4
#define TPT_X 4               // outputs per thread, x
#define TPT_Y 4               // outputs per thread, y
#define TILE_W (BX * TPT_X)   // 128
#define TILE_H (BY * TPT_Y)   // 16
#define SM_W (TILE_W + 4)     // 132
#define SM_H (TILE_H + 4)     // 20

// (128, 8): 64-reg budget — granularity-aligned (multiple of 8), only -2 from
// the natural 66, unlocks the 8th CTA/SM (32 warps vs 28).
__global__ __launch_bounds__(BX * BY, 8)
void hitmiss_kernel(const float* __restrict__ in,
                    const float* __restrict__ Kh,
                    const float* __restrict__ Km,
                    float* __restrict__ out,
                    int H, int W, int Hout, int Wout)
{
    __shared__ __align__(16) float tile[SM_H][SM_W];   // 10.3 KB

    const int tid  = threadIdx.y * BX + threadIdx.x;
    const int col0 = blockIdx.x * TILE_W;
    const int row0 = blockIdx.y * TILE_H;

    const bool interior = (row0 + SM_H <= H) && (col0 + SM_W <= W);

    // --- taps via vectorized broadcast loads: 13 LDG instead of 50 ---
    float kh[25], km[25];
    {
        const float4* Kh4 = reinterpret_cast<const float4*>(Kh);
        const float4* Km4 = reinterpret_cast<const float4*>(Km);
#pragma unroll
        for (int i = 0; i < 6; ++i) {
            float4 a = __ldg(Kh4 + i);
            kh[4*i+0] = a.x; kh[4*i+1] = a.y; kh[4*i+2] = a.z; kh[4*i+3] = a.w;
            float4 b = __ldg(Km4 + i);
            km[4*i+0] = b.x; km[4*i+1] = b.y; km[4*i+2] = b.z; km[4*i+3] = b.w;
        }
        kh[24] = __ldg(Kh + 24);
        km[24] = __ldg(Km + 24);
    }

    if (interior) {
        // --- fast loader: straight-line 2D indexing, all LDG.128 aligned ---
        const float* base = in + (size_t)row0 * W + col0;
        const int tx4 = threadIdx.x * 4;
#pragma unroll
        for (int i = 0; i < 4; ++i) {                 // rows 0..15
            const int r = threadIdx.y + 4 * i;
            *reinterpret_cast<float4*>(&tile[r][tx4]) =
                *reinterpret_cast<const float4*>(base + (size_t)r * W + tx4);
        }
        {                                             // rows 16..19
            const int r = 16 + threadIdx.y;
            *reinterpret_cast<float4*>(&tile[r][tx4]) =
                *reinterpret_cast<const float4*>(base + (size_t)r * W + tx4);
        }
        if (tid < SM_H) {                             // last float4 column (128..131)
            *reinterpret_cast<float4*>(&tile[tid][TILE_W]) =
                *reinterpret_cast<const float4*>(base + (size_t)tid * W + TILE_W);
        }
    } else {
        // --- boundary loader (rare): generic with clamps ---
        const int NW4 = SM_W / 4;          // 33
        const int NV  = NW4 * SM_H;        // 660 float4 slots
        for (int idx = tid; idx < NV; idx += BX * BY) {
            int r  = idx / NW4;
            int c4 = idx - r * NW4;
            int gr = row0 + r; if (gr > H - 1) gr = H - 1;
            int gc = col0 + c4 * 4;
            float4 v;
            if (gc + 3 <= W - 1) {
                v = *reinterpret_cast<const float4*>(in + (size_t)gr * W + gc);
            } else {
                int c0 = gc     < W - 1 ? gc     : W - 1;
                int c1 = gc + 1 < W - 1 ? gc + 1 : W - 1;
                int c2 = gc + 2 < W - 1 ? gc + 2 : W - 1;
                int c3 = gc + 3 < W - 1 ? gc + 3 : W - 1;
                const float* rowp = in + (size_t)gr * W;
                v.x = rowp[c0]; v.y = rowp[c1]; v.z = rowp[c2]; v.w = rowp[c3];
            }
            *reinterpret_cast<float4*>(&tile[r][c4 * 4]) = v;
        }
    }
    __syncthreads();

    // --- 4x4 register-blocked hit-or-miss, ROW-PAIR streaming.
    //     Two rows per iteration -> 10-leaf reduction trees (5 FMNMX3-shaped
    //     ops vs 6 for two separate rows). Avg 12.5 min-ops/output vs 14. ---
    const int lx = threadIdx.x * TPT_X;   // multiple of 4 -> aligned LDS.128
    const int ly = threadIdx.y * TPT_Y;

    float mn[TPT_Y * TPT_X], mx[TPT_Y * TPT_X];

#pragma unroll
    for (int rp = 0; rp < 4; ++rp) {               // row pairs (2rp, 2rp+1)
        float w0[8], w1[8];
        {
            float4 a = *reinterpret_cast<const float4*>(&tile[ly + 2*rp][lx]);
            float4 b = *reinterpret_cast<const float4*>(&tile[ly + 2*rp][lx + 4]);
            w0[0]=a.x; w0[1]=a.y; w0[2]=a.z; w0[3]=a.w;
            w0[4]=b.x; w0[5]=b.y; w0[6]=b.z; w0[7]=b.w;
            float4 c = *reinterpret_cast<const float4*>(&tile[ly + 2*rp + 1][lx]);
            float4 d = *reinterpret_cast<const float4*>(&tile[ly + 2*rp + 1][lx + 4]);
            w1[0]=c.x; w1[1]=c.y; w1[2]=c.z; w1[3]=c.w;
            w1[4]=d.x; w1[5]=d.y; w1[6]=d.z; w1[7]=d.w;
        }

#pragma unroll
        for (int orow = 0; orow < TPT_Y; ++orow) {
            const int di0 = 2 * rp - orow;           // compile-time constants
            const int di1 = di0 + 1;
#pragma unroll
            for (int oc = 0; oc < TPT_X; ++oc) {
                const int o = orow * TPT_X + oc;

                if (di0 >= 0 && di1 <= 4) {
                    // --- pair: 10 subs + 5-op reduction tree ---
                    float h0 = w0[oc + 0] - kh[di0*5 + 0];
                    float h1 = w0[oc + 1] - kh[di0*5 + 1];
                    float h2 = w0[oc + 2] - kh[di0*5 + 2];
                    float h3 = w0[oc + 3] - kh[di0*5 + 3];
                    float h4 = w0[oc + 4] - kh[di0*5 + 4];
                    float h5 = w1[oc + 0] - kh[di1*5 + 0];
                    float h6 = w1[oc + 1] - kh[di1*5 + 1];
                    float h7 = w1[oc + 2] - kh[di1*5 + 2];
                    float h8 = w1[oc + 3] - kh[di1*5 + 3];
                    float h9 = w1[oc + 4] - kh[di1*5 + 4];

                    float tA = fminf(fminf(h0, h1), h2);     // FMNMX3
                    float tB = fminf(fminf(h3, h4), h5);     // FMNMX3
                    float tC = fminf(fminf(h6, h7), h8);     // FMNMX3
                    float tD = fminf(fminf(tA, tB), h9);     // FMNMX3
                    if (di0 == 0) mn[o] = fminf(tC, tD);
                    else          mn[o] = fminf(fminf(tC, tD), mn[o]);  // FMNMX3

                    float m0 = w0[oc + 0] - km[di0*5 + 0];
                    float m1 = w0[oc + 1] - km[di0*5 + 1];
                    float m2 = w0[oc + 2] - km[di0*5 + 2];
                    float m3 = w0[oc + 3] - km[di0*5 + 3];
                    float m4 = w0[oc + 4] - km[di0*5 + 4];
                    float m5 = w1[oc + 0] - km[di1*5 + 0];
                    float m6 = w1[oc + 1] - km[di1*5 + 1];
                    float m7 = w1[oc + 2] - km[di1*5 + 2];
                    float m8 = w1[oc + 3] - km[di1*5 + 3];
                    float m9 = w1[oc + 4] - km[di1*5 + 4];

                    float uA = fmaxf(fmaxf(m0, m1), m2);
                    float uB = fmaxf(fmaxf(m3, m4), m5);
                    float uC = fmaxf(fmaxf(m6, m7), m8);
                    float uD = fmaxf(fmaxf(uA, uB), m9);
                    if (di0 == 0) mx[o] = fmaxf(uC, uD);
                    else          mx[o] = fmaxf(fmaxf(uC, uD), mx[o]);
                } else if (di1 == 0) {
                    // --- solo init: row di=0 lives in w1 ---
                    float h0 = w1[oc + 0] - kh[0];
                    float h1 = w1[oc + 1] - kh[1];
                    float h2 = w1[oc + 2] - kh[2];
                    float h3 = w1[oc + 3] - kh[3];
                    float h4 = w1[oc + 4] - kh[4];
                    mn[o] = fminf(fminf(fminf(fminf(h0, h1), h2), h3), h4);
                    float m0 = w1[oc + 0] - km[0];
                    float m1 = w1[oc + 1] - km[1];
                    float m2 = w1[oc + 2] - km[2];
                    float m3 = w1[oc + 3] - km[3];
                    float m4 = w1[oc + 4] - km[4];
                    mx[o] = fmaxf(fmaxf(fmaxf(fmaxf(m0, m1), m2), m3), m4);
                } else if (di0 == 4) {
                    // --- solo tail: row di=4 lives in w0, merge accumulator ---
                    float h0 = w0[oc + 0] - kh[20];
                    float h1 = w0[oc + 1] - kh[21];
                    float h2 = w0[oc + 2] - kh[22];
                    float h3 = w0[oc + 3] - kh[23];
                    float h4 = w0[oc + 4] - kh[24];
                    float tA = fminf(fminf(h0, h1), h2);
                    float tB = fminf(fminf(h3, h4), mn[o]);
                    mn[o] = fminf(tA, tB);
                    float m0 = w0[oc + 0] - km[20];
                    float m1 = w0[oc + 1] - km[21];
                    float m2 = w0[oc + 2] - km[22];
                    float m3 = w0[oc + 3] - km[23];
                    float m4 = w0[oc + 4] - km[24];
                    float uA = fmaxf(fmaxf(m0, m1), m2);
                    float uB = fmaxf(fmaxf(m3, m4), mx[o]);
                    mx[o] = fmaxf(uA, uB);
                }
                // other di0 values: this output untouched this iteration
            }
        }
    }

    // --- stores ---
    const int oc0 = col0 + lx;
    const int or0 = row0 + ly;
    if (interior && (oc0 + 3 < Wout) && (or0 + TPT_Y <= Hout)) {
        float* p = out + (size_t)or0 * Wout + oc0;
#pragma unroll
        for (int orow = 0; orow < TPT_Y; ++orow) {
            float4 o;
            o.x = mn[orow * TPT_X + 0] - mx[orow * TPT_X + 0];
            o.y = mn[orow * TPT_X + 1] - mx[orow * TPT_X + 1];
            o.z = mn[orow * TPT_X + 2] - mx[orow * TPT_X + 2];
            o.w = mn[orow * TPT_X + 3] - mx[orow * TPT_X + 3];
            *reinterpret_cast<float4*>(p) = o;
            p += Wout;
        }
    } else {
#pragma unroll
        for (int orow = 0; orow < TPT_Y; ++orow) {
            const int gro = or0 + orow;
            if (gro >= Hout) continue;
            float r0 = mn[orow * TPT_X + 0] - mx[orow * TPT_X + 0];
            float r1 = mn[orow * TPT_X + 1] - mx[orow * TPT_X + 1];
            float r2 = mn[orow * TPT_X + 2] - mx[orow * TPT_X + 2];
            float r3 = mn[orow * TPT_X + 3] - mx[orow * TPT_X + 3];
            float* orow_p = out + (size_t)gro * Wout;
            if (oc0 + 0 < Wout) orow_p[oc0 + 0] = r0;
            if (oc0 + 1 < Wout) orow_p[oc0 + 1] = r1;
            if (oc0 + 2 < Wout) orow_p[oc0 + 2] = r2;
            if (oc0 + 3 < Wout) orow_p[oc0 + 3] = r3;
        }
    }
}

extern "C" void kernel_launch(void* const* d_in, const int* in_sizes, int n_in,
                              void* d_out, int out_size)
{
    const float* in = (const float*)d_in[0];
    const float* Kh = (const float*)d_in[1];
    const float* Km = (const float*)d_in[2];
    float* out = (float*)d_out;

    const int H = (int)lround(sqrt((double)in_sizes[0]));
    const int W = H;
    const int Hout = H - 4;
    const int Wout = W - 4;

    dim3 block(BX, BY);
    dim3 grid((Wout + TILE_W - 1) / TILE_W, (Hout + TILE_H - 1) / TILE_H);
    hitmiss_kernel<<<grid, block>>>(in, Kh, Km, out, H, W, Hout, Wout);
}